// round 1
// baseline (speedup 1.0000x reference)
#include <cuda_runtime.h>
#include <cmath>
#include <cstring>
#include <algorithm>

// ---------------------------------------------------------------------------
// Problem constants
// ---------------------------------------------------------------------------
#define TT   480          // time length
#define PP   15           // period
#define NSUB 32           // TT / PP
#define TE   510          // TT + 2*PP (extended seasonal series)
#define CC   256          // channels
#define BBATCH 128        // batch

// Composed linear operator: trend = A @ y  (per series)
__device__ float g_A[TT * TT];

typedef unsigned long long u64;

// ---------------------------------------------------------------------------
// packed f32x2 helpers (Blackwell 2x fp32 FMA path)
// ---------------------------------------------------------------------------
__device__ __forceinline__ u64 pack2(float v) {
    u64 r;
    asm("mov.b64 %0, {%1, %2};" : "=l"(r) : "f"(v), "f"(v));
    return r;
}
__device__ __forceinline__ float2 unpack2(u64 v) {
    float2 f;
    asm("mov.b64 {%0, %1}, %2;" : "=f"(f.x), "=f"(f.y) : "l"(v));
    return f;
}
__device__ __forceinline__ void fma2(u64 &d, u64 a, u64 b) {
    asm("fma.rn.f32x2 %0, %1, %2, %0;" : "+l"(d) : "l"(a), "l"(b));
}

// ---------------------------------------------------------------------------
// GEMM kernel: per batch b: trend[t][c] = sum_k A[t][k] * x[b][k][c]
// out[0 .. N)   = x - trend   (== seasonal + resid, exactly)
// out[N .. 2N)  = trend
// Tiling: BM=96 (t), BN=128 (c), BK=16, 256 threads, TM=6 x TN=8 per thread.
// ---------------------------------------------------------------------------
__global__ __launch_bounds__(256) void stl_gemm_kernel(
    const float* __restrict__ x, float* __restrict__ out)
{
    __shared__ __align__(16) float As[16][97];    // [k][t], +1 pad (conflict-free store)
    __shared__ __align__(16) float Xs[16][128];   // [k][c]

    const int b  = blockIdx.z;
    const int t0 = blockIdx.y * 96;
    const int c0 = blockIdx.x * 128;
    const int tid = threadIdx.x;
    const int tx = tid & 15;    // col group: cols tx*8 .. tx*8+7
    const int ty = tid >> 4;    // row group: rows ty + 16*i, i<6

    const float* Xb = x + (size_t)b * (TT * CC);

    float  aReg[6];
    float4 xReg[2];

    // preload k-tile 0
#pragma unroll
    for (int i = 0; i < 6; i++) {
        int idx = tid + i * 256;
        int r = idx >> 4, c = idx & 15;
        aReg[i] = g_A[(t0 + r) * TT + c];
    }
#pragma unroll
    for (int i = 0; i < 2; i++) {
        int idx = tid + i * 256;
        int r = idx >> 5, c4 = idx & 31;
        xReg[i] = *(const float4*)(Xb + (size_t)r * CC + c0 + c4 * 4);
    }

    u64 acc[6][4];
#pragma unroll
    for (int i = 0; i < 6; i++)
#pragma unroll
        for (int j = 0; j < 4; j++) acc[i][j] = 0ULL;

    for (int kt = 0; kt < TT / 16; kt++) {
        // commit staged regs to smem
#pragma unroll
        for (int i = 0; i < 6; i++) {
            int idx = tid + i * 256;
            int r = idx >> 4, c = idx & 15;
            As[c][r] = aReg[i];
        }
#pragma unroll
        for (int i = 0; i < 2; i++) {
            int idx = tid + i * 256;
            int r = idx >> 5, c4 = idx & 31;
            *(float4*)(&Xs[r][c4 * 4]) = xReg[i];
        }
        __syncthreads();

        // prefetch next k-tile (global -> regs) while computing
        if (kt + 1 < TT / 16) {
            int k0 = (kt + 1) * 16;
#pragma unroll
            for (int i = 0; i < 6; i++) {
                int idx = tid + i * 256;
                int r = idx >> 4, c = idx & 15;
                aReg[i] = g_A[(t0 + r) * TT + k0 + c];
            }
#pragma unroll
            for (int i = 0; i < 2; i++) {
                int idx = tid + i * 256;
                int r = idx >> 5, c4 = idx & 31;
                xReg[i] = *(const float4*)(Xb + (size_t)(k0 + r) * CC + c0 + c4 * 4);
            }
        }

#pragma unroll
        for (int kk = 0; kk < 16; kk++) {
            u64 bfr[4];
            const u64* xp = (const u64*)(&Xs[kk][tx * 8]);
#pragma unroll
            for (int j = 0; j < 4; j++) bfr[j] = xp[j];
#pragma unroll
            for (int i = 0; i < 6; i++) {
                u64 aa = pack2(As[kk][ty + 16 * i]);
#pragma unroll
                for (int j = 0; j < 4; j++) fma2(acc[i][j], aa, bfr[j]);
            }
        }
        __syncthreads();
    }

    // epilogue: out1 = x - trend, out2 = trend
    const size_t N = (size_t)BBATCH * TT * CC;
#pragma unroll
    for (int i = 0; i < 6; i++) {
        int t = t0 + ty + 16 * i;
        size_t base = ((size_t)b * TT + t) * CC + c0 + tx * 8;
#pragma unroll
        for (int h = 0; h < 2; h++) {
            float2 p0 = unpack2(acc[i][2 * h]);
            float2 p1 = unpack2(acc[i][2 * h + 1]);
            float4 tr = make_float4(p0.x, p0.y, p1.x, p1.y);
            float4 xv = *(const float4*)(x + base + h * 4);
            float4 o1 = make_float4(xv.x - tr.x, xv.y - tr.y, xv.z - tr.z, xv.w - tr.w);
            *(float4*)(out + base + h * 4) = o1;
            *(float4*)(out + N + base + h * 4) = tr;
        }
    }
}

// ---------------------------------------------------------------------------
// Host: compose the STL operator A in float64 (deterministic every call).
// ---------------------------------------------------------------------------
static double h_MS[34 * NSUB];
static double h_MLP[(size_t)TT * TT];
static double h_MT[(size_t)TT * TT];
static double h_K1[(size_t)TT * TE];
static double h_S[(size_t)TT * TT];
static double h_G[(size_t)TT * TT];
static double h_T1[(size_t)TT * TT];
static double h_A[(size_t)TT * TT];
static float  h_Af[(size_t)TT * TT];

// degree-1 LOESS smoothing matrix (matches reference _loess_matrix, rows for
// t = t_lo .. t_lo+nts-1). Entries rounded through float32 like the reference.
static void loess_mat(int n, int q, int t_lo, int nts, double* M)
{
    int qq = q < n ? q : n;
    memset(M, 0, sizeof(double) * (size_t)nts * n);
    for (int i = 0; i < nts; i++) {
        int t = t_lo + i;
        int left = t - (q - 1) / 2;
        if (left < 0) left = 0;
        if (left > n - qq) left = n - qq;
        int right = left + qq - 1;
        double h = (double)std::max(t - left, right - t);
        if (q > n) h += (q - n) / 2.0;
        double w[64], wsum = 0.0;
        for (int j = 0; j < qq; j++) {
            double u = std::fabs((double)(left + j - t)) / h;
            double c = 1.0 - u * u * u;
            if (c < 0.0) c = 0.0;
            w[j] = c * c * c;
            wsum += w[j];
        }
        for (int j = 0; j < qq; j++) w[j] /= wsum;
        double xbar = 0.0;
        for (int j = 0; j < qq; j++) xbar += w[j] * (double)(left + j);
        double var = 0.0;
        for (int j = 0; j < qq; j++) {
            double d = (double)(left + j) - xbar;
            var += w[j] * d * d;
        }
        for (int j = 0; j < qq; j++) {
            double a = w[j];
            if (var > 1e-12)
                a = w[j] * (1.0 + ((double)t - xbar) * ((double)(left + j) - xbar) / var);
            M[(size_t)i * n + left + j] = (double)(float)a;  // .astype(float32)
        }
    }
}

// Z = X @ Y, 480x480, skipping exact-zero entries of X (LOESS rows are banded)
static void mm480(const double* __restrict__ X, const double* __restrict__ Y,
                  double* __restrict__ Z)
{
    for (int i = 0; i < TT; i++) {
        double* Zi = Z + (size_t)i * TT;
        for (int j = 0; j < TT; j++) Zi[j] = 0.0;
        const double* Xi = X + (size_t)i * TT;
        for (int k = 0; k < TT; k++) {
            double a = Xi[k];
            if (a == 0.0) continue;
            const double* Yk = Y + (size_t)k * TT;
            for (int j = 0; j < TT; j++) Zi[j] += a * Yk[j];
        }
    }
}

static void build_operator()
{
    // base LOESS matrices
    loess_mat(NSUB, 7,  -1, 34, h_MS);    // seasonal, evaluated at -1..n_sub
    loess_mat(TT,   17,  0, TT, h_MLP);   // low-pass
    loess_mat(TT,   29,  0, TT, h_MT);    // trend

    // combined MA kernel: box15 * box15 * box3, length 31
    double w31[31];
    for (int d = 0; d < 31; d++) w31[d] = 0.0;
    for (int a = 0; a < 3; a++)
        for (int b = 0; b < 15; b++)
            for (int c = 0; c < 15; c++)
                w31[a + b + c] += 1.0;
    for (int d = 0; d < 31; d++) w31[d] /= 675.0;

    // K1 = M_lp @ Mma   (480 x 510)
    memset(h_K1, 0, sizeof(h_K1));
    for (int t = 0; t < TT; t++) {
        double* Kt = h_K1 + (size_t)t * TE;
        const double* Lt = h_MLP + (size_t)t * TT;
        for (int i = 0; i < TT; i++) {
            double m = Lt[i];
            if (m == 0.0) continue;
            for (int d = 0; d < 31; d++) Kt[i + d] += m * w31[d];
        }
    }
    // B1 = P - K1 (in place): P[t, t+15] = 1
    for (size_t i = 0; i < (size_t)TT * TE; i++) h_K1[i] = -h_K1[i];
    for (int t = 0; t < TT; t++) h_K1[(size_t)t * TE + t + PP] += 1.0;

    // S = B1 @ E  where E[s*15+j, n*15+j] = MS[s, n]
    memset(h_S, 0, sizeof(h_S));
    for (int t = 0; t < TT; t++) {
        double* St = h_S + (size_t)t * TT;
        const double* Bt = h_K1 + (size_t)t * TE;
        for (int j = 0; j < PP; j++) {
            for (int s = 0; s < 34; s++) {
                double v = Bt[s * PP + j];
                if (v == 0.0) continue;
                const double* MSs = h_MS + (size_t)s * NSUB;
                for (int n = 0; n < NSUB; n++)
                    St[n * PP + j] += v * MSs[n];
            }
        }
    }

    // A = M_t (I - S (I - M_t (I - S)))
    for (int i = 0; i < TT; i++)
        for (int j = 0; j < TT; j++)
            h_G[(size_t)i * TT + j] = (i == j ? 1.0 : 0.0) - h_S[(size_t)i * TT + j];
    mm480(h_MT, h_G, h_T1);                                   // T1 = M_t(I-S)
    for (int i = 0; i < TT; i++)
        for (int j = 0; j < TT; j++)
            h_G[(size_t)i * TT + j] = (i == j ? 1.0 : 0.0) - h_T1[(size_t)i * TT + j];
    mm480(h_S, h_G, h_A);                                     // S2 = S(I-T1)
    for (int i = 0; i < TT; i++)
        for (int j = 0; j < TT; j++)
            h_G[(size_t)i * TT + j] = (i == j ? 1.0 : 0.0) - h_A[(size_t)i * TT + j];
    mm480(h_MT, h_G, h_A);                                    // A = M_t(I-S2)

    for (size_t i = 0; i < (size_t)TT * TT; i++) h_Af[i] = (float)h_A[i];
}

// ---------------------------------------------------------------------------
// kernel_launch
// ---------------------------------------------------------------------------
extern "C" void kernel_launch(void* const* d_in, const int* in_sizes, int n_in,
                              void* d_out, int out_size)
{
    (void)in_sizes; (void)n_in; (void)out_size;

    build_operator();  // host float64, runs only at correctness/capture time

    cudaMemcpyToSymbolAsync(g_A, h_Af, sizeof(h_Af), 0,
                            cudaMemcpyHostToDevice, 0);

    const float* x = (const float*)d_in[0];
    float* out = (float*)d_out;

    dim3 grid(CC / 128, TT / 96, BBATCH);   // (2, 5, 128)
    stl_gemm_kernel<<<grid, 256>>>(x, out);
}

// round 3
// speedup vs baseline: 2.9042x; 2.9042x over previous
#include <cuda_runtime.h>
#include <cstdint>
#include <cmath>
#include <cstring>
#include <algorithm>

// ---------------------------------------------------------------------------
// Problem constants
// ---------------------------------------------------------------------------
#define TT   480
#define PP   15
#define NSUB 32
#define TE   510
#define CC   256
#define BB   128
#define TPAD 512
#define NCH  30            // K chunks of 16
#define KPAD 20            // A smem row pad (floats)
#define CPAD 132           // X smem row pad (floats)

__device__ float g_A[TPAD * TT];   // padded operator, rows 480..511 = 0

// ---------------------------------------------------------------------------
// PTX helpers (all sm_80-portable)
// ---------------------------------------------------------------------------
__device__ __forceinline__ uint32_t smem_u32(const void* p) {
    uint32_t a;
    asm("{ .reg .u64 t; cvta.to.shared.u64 t, %1; cvt.u32.u64 %0, t; }"
        : "=r"(a) : "l"(p));
    return a;
}
__device__ __forceinline__ void cp16(uint32_t dst, const void* src) {
    asm volatile("cp.async.cg.shared.global [%0], [%1], 16;" :: "r"(dst), "l"(src));
}
#define CP_COMMIT() asm volatile("cp.async.commit_group;" ::: "memory")
#define CP_WAIT(n)  asm volatile("cp.async.wait_group %0;" :: "n"(n) : "memory")

__device__ __forceinline__ void mma_tf32(float* d, const uint32_t* a,
                                         const uint32_t* b) {
    asm volatile(
        "mma.sync.aligned.m16n8k8.row.col.f32.tf32.tf32.f32 "
        "{%0,%1,%2,%3}, {%4,%5,%6,%7}, {%8,%9}, {%0,%1,%2,%3};"
        : "+f"(d[0]), "+f"(d[1]), "+f"(d[2]), "+f"(d[3])
        : "r"(a[0]), "r"(a[1]), "r"(a[2]), "r"(a[3]),
          "r"(b[0]), "r"(b[1]));
}

// ---------------------------------------------------------------------------
// GEMM: per CTA: batch b, 128 t-rows (A padded to 512), 128 channels.
// trend = A @ x ; out[0..N) = x - trend ; out[N..2N) = trend
// 256 threads = 8 warps in 2(M) x 4(N); warp tile 64x32; BK=16.
// ---------------------------------------------------------------------------
__global__ void __launch_bounds__(256, 2) stl_mma_kernel(
    const float* __restrict__ x, float* __restrict__ out)
{
    __shared__ __align__(16) float As[2][128][KPAD];
    __shared__ __align__(16) float Xs[2][16][CPAD];

    const int tid = threadIdx.x;
    const int lane = tid & 31, wid = tid >> 5;
    const int warpM = wid & 1, warpN = wid >> 1;
    const int t0 = blockIdx.x * 128;
    const int c0 = blockIdx.y * 128;
    const int b  = blockIdx.z;

    const float* gAr = g_A + (size_t)t0 * TT;              // [t][k]
    const float* gXr = x + (size_t)b * TT * CC + c0;       // [k][c]

    // loader index precompute
    const int la_r0 = tid >> 2,        la_c = (tid & 3) * 4;        // A unit 0
    const int la_r1 = (tid + 256) >> 2;                             // A unit 1
    const int lx_r0 = tid >> 5,        lx_c = (tid & 31) * 4;       // X unit 0
    const int lx_r1 = (tid + 256) >> 5;                             // X unit 1

    auto issue = [&](int kt) {
        const int st = kt & 1;
        const int k0 = kt * 16;
        cp16(smem_u32(&As[st][la_r0][la_c]), gAr + (size_t)la_r0 * TT + k0 + la_c);
        cp16(smem_u32(&As[st][la_r1][la_c]), gAr + (size_t)la_r1 * TT + k0 + la_c);
        cp16(smem_u32(&Xs[st][lx_r0][lx_c]), gXr + (size_t)(k0 + lx_r0) * CC + lx_c);
        cp16(smem_u32(&Xs[st][lx_r1][lx_c]), gXr + (size_t)(k0 + lx_r1) * CC + lx_c);
        CP_COMMIT();
    };

    float acc[4][4][4];
#pragma unroll
    for (int mi = 0; mi < 4; mi++)
#pragma unroll
        for (int nj = 0; nj < 4; nj++)
#pragma unroll
            for (int r = 0; r < 4; r++) acc[mi][nj][r] = 0.0f;

    const int lr = lane >> 2, lc = lane & 3;

    issue(0);
    for (int kt = 0; kt < NCH; kt++) {
        if (kt + 1 < NCH) { issue(kt + 1); CP_WAIT(1); }
        else              { CP_WAIT(0); }
        __syncthreads();

        const int st = kt & 1;
#pragma unroll
        for (int kk = 0; kk < 2; kk++) {
            const int kb = kk * 8;
            uint32_t a[4][4], bf[4][2];
#pragma unroll
            for (int mi = 0; mi < 4; mi++) {
                const int r = warpM * 64 + mi * 16 + lr;
                a[mi][0] = __float_as_uint(As[st][r][kb + lc]);
                a[mi][1] = __float_as_uint(As[st][r + 8][kb + lc]);
                a[mi][2] = __float_as_uint(As[st][r][kb + lc + 4]);
                a[mi][3] = __float_as_uint(As[st][r + 8][kb + lc + 4]);
            }
#pragma unroll
            for (int nj = 0; nj < 4; nj++) {
                const int c = warpN * 32 + nj * 8 + lr;
                bf[nj][0] = __float_as_uint(Xs[st][kb + lc][c]);
                bf[nj][1] = __float_as_uint(Xs[st][kb + lc + 4][c]);
            }
#pragma unroll
            for (int mi = 0; mi < 4; mi++)
#pragma unroll
                for (int nj = 0; nj < 4; nj++)
                    mma_tf32(acc[mi][nj], a[mi], bf[nj]);
        }
        __syncthreads();
    }

    // epilogue: out1 = x - trend, out2 = trend
    const size_t NTOT = (size_t)BB * TT * CC;
#pragma unroll
    for (int mi = 0; mi < 4; mi++) {
#pragma unroll
        for (int half = 0; half < 2; half++) {
            const int t = t0 + warpM * 64 + mi * 16 + lr + half * 8;
            if (t >= TT) continue;
            const size_t rowb = ((size_t)b * TT + t) * CC + c0
                              + warpN * 32 + 2 * lc;
#pragma unroll
            for (int nj = 0; nj < 4; nj++) {
                const size_t o = rowb + nj * 8;
                const float2 xv = *(const float2*)(x + o);
                float2 tr;
                tr.x = acc[mi][nj][2 * half + 0];
                tr.y = acc[mi][nj][2 * half + 1];
                *(float2*)(out + o) = make_float2(xv.x - tr.x, xv.y - tr.y);
                *(float2*)(out + NTOT + o) = tr;
            }
        }
    }
}

// ---------------------------------------------------------------------------
// Host: compose the STL trend operator A (float64), round to tf32.
// ---------------------------------------------------------------------------
static double h_MS[34 * NSUB];
static double h_MLP[(size_t)TT * TT];
static double h_MT[(size_t)TT * TT];
static double h_K1[(size_t)TT * TE];
static double h_S[(size_t)TT * TT];
static double h_G[(size_t)TT * TT];
static double h_T1[(size_t)TT * TT];
static double h_A[(size_t)TT * TT];
static float  h_Af[(size_t)TPAD * TT];

static void loess_mat(int n, int q, int t_lo, int nts, double* M)
{
    int qq = q < n ? q : n;
    memset(M, 0, sizeof(double) * (size_t)nts * n);
    for (int i = 0; i < nts; i++) {
        int t = t_lo + i;
        int left = t - (q - 1) / 2;
        if (left < 0) left = 0;
        if (left > n - qq) left = n - qq;
        int right = left + qq - 1;
        double h = (double)std::max(t - left, right - t);
        if (q > n) h += (q - n) / 2.0;
        double w[64], wsum = 0.0;
        for (int j = 0; j < qq; j++) {
            double u = std::fabs((double)(left + j - t)) / h;
            double c = 1.0 - u * u * u;
            if (c < 0.0) c = 0.0;
            w[j] = c * c * c;
            wsum += w[j];
        }
        for (int j = 0; j < qq; j++) w[j] /= wsum;
        double xbar = 0.0;
        for (int j = 0; j < qq; j++) xbar += w[j] * (double)(left + j);
        double var = 0.0;
        for (int j = 0; j < qq; j++) {
            double d = (double)(left + j) - xbar;
            var += w[j] * d * d;
        }
        for (int j = 0; j < qq; j++) {
            double a = w[j];
            if (var > 1e-12)
                a = w[j] * (1.0 + ((double)t - xbar) * ((double)(left + j) - xbar) / var);
            M[(size_t)i * n + left + j] = (double)(float)a;
        }
    }
}

static void mm480(const double* __restrict__ X, const double* __restrict__ Y,
                  double* __restrict__ Z)
{
    for (int i = 0; i < TT; i++) {
        double* Zi = Z + (size_t)i * TT;
        for (int j = 0; j < TT; j++) Zi[j] = 0.0;
        const double* Xi = X + (size_t)i * TT;
        for (int k = 0; k < TT; k++) {
            double a = Xi[k];
            if (a == 0.0) continue;
            const double* Yk = Y + (size_t)k * TT;
            for (int j = 0; j < TT; j++) Zi[j] += a * Yk[j];
        }
    }
}

static float to_tf32(float v)   // round-to-nearest-even into 10-bit mantissa
{
    uint32_t u;
    memcpy(&u, &v, 4);
    uint32_t r = (u + 0xFFFu + ((u >> 13) & 1u)) & ~0x1FFFu;
    float f;
    memcpy(&f, &r, 4);
    return f;
}

static void build_operator()
{
    loess_mat(NSUB, 7,  -1, 34, h_MS);
    loess_mat(TT,   17,  0, TT, h_MLP);
    loess_mat(TT,   29,  0, TT, h_MT);

    double w31[31];
    for (int d = 0; d < 31; d++) w31[d] = 0.0;
    for (int a = 0; a < 3; a++)
        for (int b = 0; b < 15; b++)
            for (int c = 0; c < 15; c++)
                w31[a + b + c] += 1.0;
    for (int d = 0; d < 31; d++) w31[d] /= 675.0;

    memset(h_K1, 0, sizeof(h_K1));
    for (int t = 0; t < TT; t++) {
        double* Kt = h_K1 + (size_t)t * TE;
        const double* Lt = h_MLP + (size_t)t * TT;
        for (int i = 0; i < TT; i++) {
            double m = Lt[i];
            if (m == 0.0) continue;
            for (int d = 0; d < 31; d++) Kt[i + d] += m * w31[d];
        }
    }
    for (size_t i = 0; i < (size_t)TT * TE; i++) h_K1[i] = -h_K1[i];
    for (int t = 0; t < TT; t++) h_K1[(size_t)t * TE + t + PP] += 1.0;

    memset(h_S, 0, sizeof(h_S));
    for (int t = 0; t < TT; t++) {
        double* St = h_S + (size_t)t * TT;
        const double* Bt = h_K1 + (size_t)t * TE;
        for (int j = 0; j < PP; j++) {
            for (int s = 0; s < 34; s++) {
                double v = Bt[s * PP + j];
                if (v == 0.0) continue;
                const double* MSs = h_MS + (size_t)s * NSUB;
                for (int n = 0; n < NSUB; n++)
                    St[n * PP + j] += v * MSs[n];
            }
        }
    }

    for (int i = 0; i < TT; i++)
        for (int j = 0; j < TT; j++)
            h_G[(size_t)i * TT + j] = (i == j ? 1.0 : 0.0) - h_S[(size_t)i * TT + j];
    mm480(h_MT, h_G, h_T1);
    for (int i = 0; i < TT; i++)
        for (int j = 0; j < TT; j++)
            h_G[(size_t)i * TT + j] = (i == j ? 1.0 : 0.0) - h_T1[(size_t)i * TT + j];
    mm480(h_S, h_G, h_A);
    for (int i = 0; i < TT; i++)
        for (int j = 0; j < TT; j++)
            h_G[(size_t)i * TT + j] = (i == j ? 1.0 : 0.0) - h_A[(size_t)i * TT + j];
    mm480(h_MT, h_G, h_A);

    memset(h_Af, 0, sizeof(h_Af));
    for (int i = 0; i < TT; i++)
        for (int j = 0; j < TT; j++)
            h_Af[(size_t)i * TT + j] = to_tf32((float)h_A[(size_t)i * TT + j]);
}

// ---------------------------------------------------------------------------
// kernel_launch
// ---------------------------------------------------------------------------
extern "C" void kernel_launch(void* const* d_in, const int* in_sizes, int n_in,
                              void* d_out, int out_size)
{
    (void)in_sizes; (void)n_in; (void)out_size;

    build_operator();

    cudaMemcpyToSymbolAsync(g_A, h_Af, sizeof(h_Af), 0,
                            cudaMemcpyHostToDevice, 0);

    const float* x = (const float*)d_in[0];
    float* out = (float*)d_out;

    dim3 grid(TPAD / 128, CC / 128, BB);   // (4, 2, 128)
    stl_mma_kernel<<<grid, 256>>>(x, out);
}

// round 5
// speedup vs baseline: 2.9395x; 1.0122x over previous
#include <cuda_runtime.h>
#include <cstdint>
#include <cmath>
#include <cstring>
#include <algorithm>

// ---------------------------------------------------------------------------
// Problem constants
// ---------------------------------------------------------------------------
#define TT   480
#define PP   15
#define NSUB 32
#define TE   510
#define CC   256
#define BB   128
#define TPAD 512
#define NCH  30            // K chunks of 16
#define KPAD 20            // A smem row pad (floats); 80B pitch
#define CPAD 132           // X smem row pad (floats)

#define AS_STRIDE (128 * KPAD)          // floats per A stage
#define XS_STRIDE (16 * CPAD)           // floats per X stage
#define SMEM_BYTES ((3 * AS_STRIDE + 3 * XS_STRIDE) * 4)

__device__ float g_A[TPAD * TT];   // padded operator, rows 480..511 = 0

// ---------------------------------------------------------------------------
// PTX helpers (sm_80-portable)
// ---------------------------------------------------------------------------
__device__ __forceinline__ uint32_t smem_u32(const void* p) {
    uint32_t a;
    asm("{ .reg .u64 t; cvta.to.shared.u64 t, %1; cvt.u32.u64 %0, t; }"
        : "=r"(a) : "l"(p));
    return a;
}
__device__ __forceinline__ void cp16(uint32_t dst, const void* src) {
    asm volatile("cp.async.cg.shared.global [%0], [%1], 16;" :: "r"(dst), "l"(src));
}
#define CP_COMMIT() asm volatile("cp.async.commit_group;" ::: "memory")
#define CP_WAIT(n)  asm volatile("cp.async.wait_group %0;" :: "n"(n) : "memory")

__device__ __forceinline__ void ldsm_x4(uint32_t* r, uint32_t addr) {
    asm volatile(
        "ldmatrix.sync.aligned.m8n8.x4.shared.b16 {%0,%1,%2,%3}, [%4];"
        : "=r"(r[0]), "=r"(r[1]), "=r"(r[2]), "=r"(r[3]) : "r"(addr));
}

__device__ __forceinline__ void mma_tf32(float* d, const uint32_t* a,
                                         const uint32_t* b) {
    asm volatile(
        "mma.sync.aligned.m16n8k8.row.col.f32.tf32.tf32.f32 "
        "{%0,%1,%2,%3}, {%4,%5,%6,%7}, {%8,%9}, {%0,%1,%2,%3};"
        : "+f"(d[0]), "+f"(d[1]), "+f"(d[2]), "+f"(d[3])
        : "r"(a[0]), "r"(a[1]), "r"(a[2]), "r"(a[3]),
          "r"(b[0]), "r"(b[1]));
}

// ---------------------------------------------------------------------------
// GEMM: per CTA: batch b, 128 t-rows (A padded to 512), 128 channels.
// trend = A @ x ; out[0..N) = x - trend ; out[N..2N) = trend
// 256 threads = 8 warps in 2(M) x 4(N); warp tile 64x32; BK=16; 3-stage.
// ---------------------------------------------------------------------------
__global__ void __launch_bounds__(256, 2) stl_mma_kernel(
    const float* __restrict__ x, float* __restrict__ out)
{
    extern __shared__ __align__(16) float smem[];
    float* AsP = smem;                    // [3][128][KPAD]
    float* XsP = smem + 3 * AS_STRIDE;    // [3][16][CPAD]

    const int tid = threadIdx.x;
    const int lane = tid & 31, wid = tid >> 5;
    const int warpM = wid & 1, warpN = wid >> 1;
    const int t0 = blockIdx.x * 128;
    const int c0 = blockIdx.y * 128;
    const int b  = blockIdx.z;

    const float* gAr = g_A + (size_t)t0 * TT;              // [t][k]
    const float* gXr = x + (size_t)b * TT * CC + c0;       // [k][c]

    // loader indices
    const int la_r0 = tid >> 2,  la_c = (tid & 3) * 4;
    const int la_r1 = la_r0 + 64;
    const int lx_r0 = tid >> 5,  lx_c = (tid & 31) * 4;
    const int lx_r1 = lx_r0 + 8;

    auto issue = [&](int kt) {
        const int st = kt % 3;
        const int k0 = kt * 16;
        float* As_st = AsP + st * AS_STRIDE;
        float* Xs_st = XsP + st * XS_STRIDE;
        cp16(smem_u32(As_st + la_r0 * KPAD + la_c), gAr + (size_t)la_r0 * TT + k0 + la_c);
        cp16(smem_u32(As_st + la_r1 * KPAD + la_c), gAr + (size_t)la_r1 * TT + k0 + la_c);
        cp16(smem_u32(Xs_st + lx_r0 * CPAD + lx_c), gXr + (size_t)(k0 + lx_r0) * CC + lx_c);
        cp16(smem_u32(Xs_st + lx_r1 * CPAD + lx_c), gXr + (size_t)(k0 + lx_r1) * CC + lx_c);
        CP_COMMIT();
    };

    float acc[4][4][4];
#pragma unroll
    for (int mi = 0; mi < 4; mi++)
#pragma unroll
        for (int nj = 0; nj < 4; nj++)
#pragma unroll
            for (int r = 0; r < 4; r++) acc[mi][nj][r] = 0.0f;

    const int lr = lane >> 2, lc = lane & 3;

    // ldmatrix per-lane address bases: matrix id m = lane>>3, row-in-matrix = lane&7
    const int lm = lane >> 3;
    const int aRowOff = ((lm & 1) << 3) + (lane & 7);   // 0..15
    const int aColB   = (lm >> 1) << 4;                 // 0 or 16 bytes
    uint32_t aAddr[4];
#pragma unroll
    for (int mi = 0; mi < 4; mi++)
        aAddr[mi] = smem_u32(AsP + (warpM * 64 + mi * 16 + aRowOff) * KPAD) + aColB;

    issue(0); issue(1);

    for (int kt = 0; kt < NCH; kt++) {
        if (kt < NCH - 1) { CP_WAIT(1); } else { CP_WAIT(0); }
        __syncthreads();
        if (kt + 2 < NCH) issue(kt + 2);

        const int st = kt % 3;
        const uint32_t aStB = (uint32_t)(st * AS_STRIDE * 4);
        const float* Xs_st = XsP + st * XS_STRIDE;
        const int cBase = warpN * 32 + lr;

#pragma unroll
        for (int kk = 0; kk < 2; kk++) {
            const int kb = kk * 8;
            uint32_t a[4][4], bf[4][2];
#pragma unroll
            for (int mi = 0; mi < 4; mi++)
                ldsm_x4(a[mi], aAddr[mi] + aStB + (uint32_t)(kk * 32));
#pragma unroll
            for (int nj = 0; nj < 4; nj++) {
                bf[nj][0] = __float_as_uint(Xs_st[(kb + lc) * CPAD + cBase + nj * 8]);
                bf[nj][1] = __float_as_uint(Xs_st[(kb + lc + 4) * CPAD + cBase + nj * 8]);
            }
#pragma unroll
            for (int mi = 0; mi < 4; mi++)
#pragma unroll
                for (int nj = 0; nj < 4; nj++)
                    mma_tf32(acc[mi][nj], a[mi], bf[nj]);
        }
    }

    // epilogue: out1 = x - trend, out2 = trend
    const size_t NTOT = (size_t)BB * TT * CC;
#pragma unroll
    for (int mi = 0; mi < 4; mi++) {
#pragma unroll
        for (int half = 0; half < 2; half++) {
            const int t = t0 + warpM * 64 + mi * 16 + lr + half * 8;
            if (t >= TT) continue;
            const size_t rowb = ((size_t)b * TT + t) * CC + c0
                              + warpN * 32 + 2 * lc;
#pragma unroll
            for (int nj = 0; nj < 4; nj++) {
                const size_t o = rowb + nj * 8;
                const float2 xv = *(const float2*)(x + o);
                float2 tr;
                tr.x = acc[mi][nj][2 * half + 0];
                tr.y = acc[mi][nj][2 * half + 1];
                *(float2*)(out + o) = make_float2(xv.x - tr.x, xv.y - tr.y);
                *(float2*)(out + NTOT + o) = tr;
            }
        }
    }
}

// ---------------------------------------------------------------------------
// Host: compose the STL trend operator A (float64), round to tf32.
// ---------------------------------------------------------------------------
static double h_MS[34 * NSUB];
static double h_MLP[(size_t)TT * TT];
static double h_MT[(size_t)TT * TT];
static double h_K1[(size_t)TT * TE];
static double h_S[(size_t)TT * TT];
static double h_G[(size_t)TT * TT];
static double h_T1[(size_t)TT * TT];
static double h_A[(size_t)TT * TT];
static float  h_Af[(size_t)TPAD * TT];

static void loess_mat(int n, int q, int t_lo, int nts, double* M)
{
    int qq = q < n ? q : n;
    memset(M, 0, sizeof(double) * (size_t)nts * n);
    for (int i = 0; i < nts; i++) {
        int t = t_lo + i;
        int left = t - (q - 1) / 2;
        if (left < 0) left = 0;
        if (left > n - qq) left = n - qq;
        int right = left + qq - 1;
        double h = (double)std::max(t - left, right - t);
        if (q > n) h += (q - n) / 2.0;
        double w[64], wsum = 0.0;
        for (int j = 0; j < qq; j++) {
            double u = std::fabs((double)(left + j - t)) / h;
            double c = 1.0 - u * u * u;
            if (c < 0.0) c = 0.0;
            w[j] = c * c * c;
            wsum += w[j];
        }
        for (int j = 0; j < qq; j++) w[j] /= wsum;
        double xbar = 0.0;
        for (int j = 0; j < qq; j++) xbar += w[j] * (double)(left + j);
        double var = 0.0;
        for (int j = 0; j < qq; j++) {
            double d = (double)(left + j) - xbar;
            var += w[j] * d * d;
        }
        for (int j = 0; j < qq; j++) {
            double a = w[j];
            if (var > 1e-12)
                a = w[j] * (1.0 + ((double)t - xbar) * ((double)(left + j) - xbar) / var);
            M[(size_t)i * n + left + j] = (double)(float)a;
        }
    }
}

static void mm480(const double* __restrict__ X, const double* __restrict__ Y,
                  double* __restrict__ Z)
{
    for (int i = 0; i < TT; i++) {
        double* Zi = Z + (size_t)i * TT;
        for (int j = 0; j < TT; j++) Zi[j] = 0.0;
        const double* Xi = X + (size_t)i * TT;
        for (int k = 0; k < TT; k++) {
            double a = Xi[k];
            if (a == 0.0) continue;
            const double* Yk = Y + (size_t)k * TT;
            for (int j = 0; j < TT; j++) Zi[j] += a * Yk[j];
        }
    }
}

static float to_tf32(float v)   // round-to-nearest into 10-bit mantissa
{
    uint32_t u;
    memcpy(&u, &v, 4);
    uint32_t r = (u + 0xFFFu + ((u >> 13) & 1u)) & ~0x1FFFu;
    float f;
    memcpy(&f, &r, 4);
    return f;
}

static void build_operator()
{
    loess_mat(NSUB, 7,  -1, 34, h_MS);
    loess_mat(TT,   17,  0, TT, h_MLP);
    loess_mat(TT,   29,  0, TT, h_MT);

    double w31[31];
    for (int d = 0; d < 31; d++) w31[d] = 0.0;
    for (int a = 0; a < 3; a++)
        for (int b = 0; b < 15; b++)
            for (int c = 0; c < 15; c++)
                w31[a + b + c] += 1.0;
    for (int d = 0; d < 31; d++) w31[d] /= 675.0;

    memset(h_K1, 0, sizeof(h_K1));
    for (int t = 0; t < TT; t++) {
        double* Kt = h_K1 + (size_t)t * TE;
        const double* Lt = h_MLP + (size_t)t * TT;
        for (int i = 0; i < TT; i++) {
            double m = Lt[i];
            if (m == 0.0) continue;
            for (int d = 0; d < 31; d++) Kt[i + d] += m * w31[d];
        }
    }
    for (size_t i = 0; i < (size_t)TT * TE; i++) h_K1[i] = -h_K1[i];
    for (int t = 0; t < TT; t++) h_K1[(size_t)t * TE + t + PP] += 1.0;

    memset(h_S, 0, sizeof(h_S));
    for (int t = 0; t < TT; t++) {
        double* St = h_S + (size_t)t * TT;
        const double* Bt = h_K1 + (size_t)t * TE;
        for (int j = 0; j < PP; j++) {
            for (int s = 0; s < 34; s++) {
                double v = Bt[s * PP + j];
                if (v == 0.0) continue;
                const double* MSs = h_MS + (size_t)s * NSUB;
                for (int n = 0; n < NSUB; n++)
                    St[n * PP + j] += v * MSs[n];
            }
        }
    }

    for (int i = 0; i < TT; i++)
        for (int j = 0; j < TT; j++)
            h_G[(size_t)i * TT + j] = (i == j ? 1.0 : 0.0) - h_S[(size_t)i * TT + j];
    mm480(h_MT, h_G, h_T1);
    for (int i = 0; i < TT; i++)
        for (int j = 0; j < TT; j++)
            h_G[(size_t)i * TT + j] = (i == j ? 1.0 : 0.0) - h_T1[(size_t)i * TT + j];
    mm480(h_S, h_G, h_A);
    for (int i = 0; i < TT; i++)
        for (int j = 0; j < TT; j++)
            h_G[(size_t)i * TT + j] = (i == j ? 1.0 : 0.0) - h_A[(size_t)i * TT + j];
    mm480(h_MT, h_G, h_A);

    memset(h_Af, 0, sizeof(h_Af));
    for (int i = 0; i < TT; i++)
        for (int j = 0; j < TT; j++)
            h_Af[(size_t)i * TT + j] = to_tf32((float)h_A[(size_t)i * TT + j]);
}

// ---------------------------------------------------------------------------
// kernel_launch  (graph-capturable ops ONLY: async memcpy + kernel launch)
// ---------------------------------------------------------------------------
extern "C" void kernel_launch(void* const* d_in, const int* in_sizes, int n_in,
                              void* d_out, int out_size)
{
    (void)in_sizes; (void)n_in; (void)out_size;

    build_operator();

    cudaFuncSetAttribute(stl_mma_kernel,
                         cudaFuncAttributeMaxDynamicSharedMemorySize, SMEM_BYTES);

    cudaMemcpyToSymbolAsync(g_A, h_Af, sizeof(h_Af), 0,
                            cudaMemcpyHostToDevice, 0);

    const float* x = (const float*)d_in[0];
    float* out = (float*)d_out;

    dim3 grid(TPAD / 128, CC / 128, BB);   // (4, 2, 128)
    stl_mma_kernel<<<grid, 256, SMEM_BYTES>>>(x, out);
}

// round 6
// speedup vs baseline: 3.1672x; 1.0774x over previous
#include <cuda_runtime.h>
#include <cstdint>
#include <cmath>
#include <cstring>
#include <algorithm>

// ---------------------------------------------------------------------------
// Problem constants
// ---------------------------------------------------------------------------
#define TT   480
#define PP   15
#define NSUB 32
#define TE   510
#define CC   256
#define BB   128
#define TPAD 512
#define NCH  15            // K chunks of 32
#define KPAD 36            // A smem row pad (floats); 144B pitch, LDSM conflict-free
#define CPAD 132           // X smem row pad (floats)

#define AS_STRIDE (128 * KPAD)          // floats per A stage (4608)
#define XS_STRIDE (32 * CPAD)           // floats per X stage (4224)
#define SMEM_BYTES ((3 * AS_STRIDE + 3 * XS_STRIDE) * 4)   // 105984 B

__device__ float g_A[TPAD * TT];   // padded operator, rows 480..511 = 0

// ---------------------------------------------------------------------------
// PTX helpers (sm_80-portable)
// ---------------------------------------------------------------------------
__device__ __forceinline__ uint32_t smem_u32(const void* p) {
    uint32_t a;
    asm("{ .reg .u64 t; cvta.to.shared.u64 t, %1; cvt.u32.u64 %0, t; }"
        : "=r"(a) : "l"(p));
    return a;
}
__device__ __forceinline__ void cp16(uint32_t dst, const void* src) {
    asm volatile("cp.async.cg.shared.global [%0], [%1], 16;" :: "r"(dst), "l"(src));
}
#define CP_COMMIT() asm volatile("cp.async.commit_group;" ::: "memory")
#define CP_WAIT(n)  asm volatile("cp.async.wait_group %0;" :: "n"(n) : "memory")

__device__ __forceinline__ void ldsm_x4(uint32_t* r, uint32_t addr) {
    asm volatile(
        "ldmatrix.sync.aligned.m8n8.x4.shared.b16 {%0,%1,%2,%3}, [%4];"
        : "=r"(r[0]), "=r"(r[1]), "=r"(r[2]), "=r"(r[3]) : "r"(addr));
}

__device__ __forceinline__ void mma_tf32(float* d, const uint32_t* a,
                                         const uint32_t* b) {
    asm volatile(
        "mma.sync.aligned.m16n8k8.row.col.f32.tf32.tf32.f32 "
        "{%0,%1,%2,%3}, {%4,%5,%6,%7}, {%8,%9}, {%0,%1,%2,%3};"
        : "+f"(d[0]), "+f"(d[1]), "+f"(d[2]), "+f"(d[3])
        : "r"(a[0]), "r"(a[1]), "r"(a[2]), "r"(a[3]),
          "r"(b[0]), "r"(b[1]));
}

// ---------------------------------------------------------------------------
// GEMM: per CTA: batch b, 128 t-rows (A padded to 512), 128 channels.
// trend = A @ x ; out[0..N) = x - trend ; out[N..2N) = trend
// 256 threads = 8 warps in 2(M) x 4(N); warp tile 64x32; BK=32; 3-stage.
// ---------------------------------------------------------------------------
__global__ void __launch_bounds__(256, 2) stl_mma_kernel(
    const float* __restrict__ x, float* __restrict__ out)
{
    extern __shared__ __align__(16) float smem[];
    float* AsP = smem;                    // [3][128][KPAD]
    float* XsP = smem + 3 * AS_STRIDE;    // [3][32][CPAD]

    const int tid = threadIdx.x;
    const int lane = tid & 31, wid = tid >> 5;
    const int warpM = wid & 1, warpN = wid >> 1;
    const int t0 = blockIdx.x * 128;
    const int c0 = blockIdx.y * 128;
    const int b  = blockIdx.z;

    const float* gAr = g_A + (size_t)t0 * TT;              // [t][k]
    const float* gXr = x + (size_t)b * TT * CC + c0;       // [k][c]

    // loader indices (BK=32): A: 1024 16B-units, X: 1024 16B-units; 4 each/thread
    const int la_r = tid >> 3, la_c = (tid & 7) * 4;       // +32 rows per unit
    const int lx_r = tid >> 5, lx_c = (tid & 31) * 4;      // +8 rows per unit

    auto issue = [&](int kt) {
        const int st = kt % 3;
        const int k0 = kt * 32;
        float* As_st = AsP + st * AS_STRIDE;
        float* Xs_st = XsP + st * XS_STRIDE;
#pragma unroll
        for (int i = 0; i < 4; i++) {
            const int r = la_r + i * 32;
            cp16(smem_u32(As_st + r * KPAD + la_c), gAr + (size_t)r * TT + k0 + la_c);
        }
#pragma unroll
        for (int i = 0; i < 4; i++) {
            const int r = lx_r + i * 8;
            cp16(smem_u32(Xs_st + r * CPAD + lx_c), gXr + (size_t)(k0 + r) * CC + lx_c);
        }
        CP_COMMIT();
    };

    float acc[4][4][4];
#pragma unroll
    for (int mi = 0; mi < 4; mi++)
#pragma unroll
        for (int nj = 0; nj < 4; nj++)
#pragma unroll
            for (int r = 0; r < 4; r++) acc[mi][nj][r] = 0.0f;

    const int lr = lane >> 2, lc = lane & 3;

    // ldmatrix per-lane base: matrix id m = lane>>3, row-in-matrix = lane&7
    const int lm = lane >> 3;
    const int aRowOff = ((lm & 1) << 3) + (lane & 7);   // 0..15
    const int aColB   = (lm >> 1) << 4;                 // 0 or 16 bytes
    uint32_t aAddr[4];
#pragma unroll
    for (int mi = 0; mi < 4; mi++)
        aAddr[mi] = smem_u32(AsP + (warpM * 64 + mi * 16 + aRowOff) * KPAD) + aColB;

    issue(0); issue(1);

    for (int kt = 0; kt < NCH; kt++) {
        if (kt < NCH - 1) { CP_WAIT(1); } else { CP_WAIT(0); }
        __syncthreads();
        if (kt + 2 < NCH) issue(kt + 2);

        const int st = kt % 3;
        const uint32_t aStB = (uint32_t)(st * AS_STRIDE * 4);
        const float* Xs_st = XsP + st * XS_STRIDE;
        const int cBase = warpN * 32 + lr;

#pragma unroll
        for (int kk = 0; kk < 4; kk++) {           // 4 k8-steps per chunk
            const int kb = kk * 8;
            uint32_t a[4][4], bf[4][2];
#pragma unroll
            for (int mi = 0; mi < 4; mi++)
                ldsm_x4(a[mi], aAddr[mi] + aStB + (uint32_t)(kk * 32));
#pragma unroll
            for (int nj = 0; nj < 4; nj++) {
                bf[nj][0] = __float_as_uint(Xs_st[(kb + lc) * CPAD + cBase + nj * 8]);
                bf[nj][1] = __float_as_uint(Xs_st[(kb + lc + 4) * CPAD + cBase + nj * 8]);
            }
#pragma unroll
            for (int mi = 0; mi < 4; mi++)
#pragma unroll
                for (int nj = 0; nj < 4; nj++)
                    mma_tf32(acc[mi][nj], a[mi], bf[nj]);
        }
    }

    // epilogue: out1 = x - trend, out2 = trend
    const size_t NTOT = (size_t)BB * TT * CC;
#pragma unroll
    for (int mi = 0; mi < 4; mi++) {
#pragma unroll
        for (int half = 0; half < 2; half++) {
            const int t = t0 + warpM * 64 + mi * 16 + lr + half * 8;
            if (t >= TT) continue;
            const size_t rowb = ((size_t)b * TT + t) * CC + c0
                              + warpN * 32 + 2 * lc;
#pragma unroll
            for (int nj = 0; nj < 4; nj++) {
                const size_t o = rowb + nj * 8;
                const float2 xv = *(const float2*)(x + o);
                float2 tr;
                tr.x = acc[mi][nj][2 * half + 0];
                tr.y = acc[mi][nj][2 * half + 1];
                *(float2*)(out + o) = make_float2(xv.x - tr.x, xv.y - tr.y);
                *(float2*)(out + NTOT + o) = tr;
            }
        }
    }
}

// ---------------------------------------------------------------------------
// Host: compose the STL trend operator A (float64), round to tf32.
// ---------------------------------------------------------------------------
static double h_MS[34 * NSUB];
static double h_MLP[(size_t)TT * TT];
static double h_MT[(size_t)TT * TT];
static double h_K1[(size_t)TT * TE];
static double h_S[(size_t)TT * TT];
static double h_G[(size_t)TT * TT];
static double h_T1[(size_t)TT * TT];
static double h_A[(size_t)TT * TT];
static float  h_Af[(size_t)TPAD * TT];

static void loess_mat(int n, int q, int t_lo, int nts, double* M)
{
    int qq = q < n ? q : n;
    memset(M, 0, sizeof(double) * (size_t)nts * n);
    for (int i = 0; i < nts; i++) {
        int t = t_lo + i;
        int left = t - (q - 1) / 2;
        if (left < 0) left = 0;
        if (left > n - qq) left = n - qq;
        int right = left + qq - 1;
        double h = (double)std::max(t - left, right - t);
        if (q > n) h += (q - n) / 2.0;
        double w[64], wsum = 0.0;
        for (int j = 0; j < qq; j++) {
            double u = std::fabs((double)(left + j - t)) / h;
            double c = 1.0 - u * u * u;
            if (c < 0.0) c = 0.0;
            w[j] = c * c * c;
            wsum += w[j];
        }
        for (int j = 0; j < qq; j++) w[j] /= wsum;
        double xbar = 0.0;
        for (int j = 0; j < qq; j++) xbar += w[j] * (double)(left + j);
        double var = 0.0;
        for (int j = 0; j < qq; j++) {
            double d = (double)(left + j) - xbar;
            var += w[j] * d * d;
        }
        for (int j = 0; j < qq; j++) {
            double a = w[j];
            if (var > 1e-12)
                a = w[j] * (1.0 + ((double)t - xbar) * ((double)(left + j) - xbar) / var);
            M[(size_t)i * n + left + j] = (double)(float)a;
        }
    }
}

static void mm480(const double* __restrict__ X, const double* __restrict__ Y,
                  double* __restrict__ Z)
{
    for (int i = 0; i < TT; i++) {
        double* Zi = Z + (size_t)i * TT;
        for (int j = 0; j < TT; j++) Zi[j] = 0.0;
        const double* Xi = X + (size_t)i * TT;
        for (int k = 0; k < TT; k++) {
            double a = Xi[k];
            if (a == 0.0) continue;
            const double* Yk = Y + (size_t)k * TT;
            for (int j = 0; j < TT; j++) Zi[j] += a * Yk[j];
        }
    }
}

static float to_tf32(float v)   // round-to-nearest into 10-bit mantissa
{
    uint32_t u;
    memcpy(&u, &v, 4);
    uint32_t r = (u + 0xFFFu + ((u >> 13) & 1u)) & ~0x1FFFu;
    float f;
    memcpy(&f, &r, 4);
    return f;
}

static void build_operator()
{
    loess_mat(NSUB, 7,  -1, 34, h_MS);
    loess_mat(TT,   17,  0, TT, h_MLP);
    loess_mat(TT,   29,  0, TT, h_MT);

    double w31[31];
    for (int d = 0; d < 31; d++) w31[d] = 0.0;
    for (int a = 0; a < 3; a++)
        for (int b = 0; b < 15; b++)
            for (int c = 0; c < 15; c++)
                w31[a + b + c] += 1.0;
    for (int d = 0; d < 31; d++) w31[d] /= 675.0;

    memset(h_K1, 0, sizeof(h_K1));
    for (int t = 0; t < TT; t++) {
        double* Kt = h_K1 + (size_t)t * TE;
        const double* Lt = h_MLP + (size_t)t * TT;
        for (int i = 0; i < TT; i++) {
            double m = Lt[i];
            if (m == 0.0) continue;
            for (int d = 0; d < 31; d++) Kt[i + d] += m * w31[d];
        }
    }
    for (size_t i = 0; i < (size_t)TT * TE; i++) h_K1[i] = -h_K1[i];
    for (int t = 0; t < TT; t++) h_K1[(size_t)t * TE + t + PP] += 1.0;

    memset(h_S, 0, sizeof(h_S));
    for (int t = 0; t < TT; t++) {
        double* St = h_S + (size_t)t * TT;
        const double* Bt = h_K1 + (size_t)t * TE;
        for (int j = 0; j < PP; j++) {
            for (int s = 0; s < 34; s++) {
                double v = Bt[s * PP + j];
                if (v == 0.0) continue;
                const double* MSs = h_MS + (size_t)s * NSUB;
                for (int n = 0; n < NSUB; n++)
                    St[n * PP + j] += v * MSs[n];
            }
        }
    }

    for (int i = 0; i < TT; i++)
        for (int j = 0; j < TT; j++)
            h_G[(size_t)i * TT + j] = (i == j ? 1.0 : 0.0) - h_S[(size_t)i * TT + j];
    mm480(h_MT, h_G, h_T1);
    for (int i = 0; i < TT; i++)
        for (int j = 0; j < TT; j++)
            h_G[(size_t)i * TT + j] = (i == j ? 1.0 : 0.0) - h_T1[(size_t)i * TT + j];
    mm480(h_S, h_G, h_A);
    for (int i = 0; i < TT; i++)
        for (int j = 0; j < TT; j++)
            h_G[(size_t)i * TT + j] = (i == j ? 1.0 : 0.0) - h_A[(size_t)i * TT + j];
    mm480(h_MT, h_G, h_A);

    memset(h_Af, 0, sizeof(h_Af));
    for (int i = 0; i < TT; i++)
        for (int j = 0; j < TT; j++)
            h_Af[(size_t)i * TT + j] = to_tf32((float)h_A[(size_t)i * TT + j]);
}

// ---------------------------------------------------------------------------
// kernel_launch  (graph-capturable ops ONLY: async memcpy + kernel launch)
// ---------------------------------------------------------------------------
extern "C" void kernel_launch(void* const* d_in, const int* in_sizes, int n_in,
                              void* d_out, int out_size)
{
    (void)in_sizes; (void)n_in; (void)out_size;

    build_operator();

    cudaFuncSetAttribute(stl_mma_kernel,
                         cudaFuncAttributeMaxDynamicSharedMemorySize, SMEM_BYTES);

    cudaMemcpyToSymbolAsync(g_A, h_Af, sizeof(h_Af), 0,
                            cudaMemcpyHostToDevice, 0);

    const float* x = (const float*)d_in[0];
    float* out = (float*)d_out;

    dim3 grid(TPAD / 128, CC / 128, BB);   // (4, 2, 128)
    stl_mma_kernel<<<grid, 256, SMEM_BYTES>>>(x, out);
}